// round 10
// baseline (speedup 1.0000x reference)
#include <cuda_runtime.h>

#define NCLS 32
#define SOSC 30
#define EOSC 31
#define LOG2E 1.4426950408889634f
#define LN2F  0.6931471805599453f

typedef unsigned long long u64;

__device__ __forceinline__ float ex2f(float x){ float r; asm("ex2.approx.f32 %0, %1;" : "=f"(r) : "f"(x)); return r; }
__device__ __forceinline__ float lg2f_(float x){ float r; asm("lg2.approx.f32 %0, %1;" : "=f"(r) : "f"(x)); return r; }
__device__ __forceinline__ u64 pk2(float lo, float hi){ u64 r; asm("mov.b64 %0, {%1,%2};" : "=l"(r) : "f"(lo), "f"(hi)); return r; }
__device__ __forceinline__ void up2(u64 v, float& lo, float& hi){ asm("mov.b64 {%0,%1}, %2;" : "=f"(lo), "=f"(hi) : "l"(v)); }
__device__ __forceinline__ u64 ffma2(u64 a, u64 b, u64 c){ u64 d; asm("fma.rn.f32x2 %0, %1, %2, %3;" : "=l"(d) : "l"(a), "l"(b), "l"(c)); return d; }
__device__ __forceinline__ u64 fadd2(u64 a, u64 b){ u64 d; asm("add.rn.f32x2 %0, %1, %2;" : "=l"(d) : "l"(a), "l"(b)); return d; }
__device__ __forceinline__ u64 fmul2(u64 a, u64 b){ u64 d; asm("mul.rn.f32x2 %0, %1, %2;" : "=l"(d) : "l"(a), "l"(b)); return d; }
__device__ __forceinline__ u64 fsub2(u64 a, u64 b){ u64 d; asm("sub.rn.f32x2 %0, %1, %2;" : "=l"(d) : "l"(a), "l"(b)); return d; }

// 64-bit idx-shuffle via two independent 32-bit shfl.idx.
__device__ __forceinline__ u64 shfl64(u64 v, int src){
    float lo, hi; up2(v, lo, hi);
    lo = __shfl_sync(0xffffffffu, lo, src);
    hi = __shfl_sync(0xffffffffu, hi, src);
    return pk2(lo, hi);
}
// 64-bit xor-shuffle.
__device__ __forceinline__ u64 shfl64x(u64 v, int m){
    float lo, hi; up2(v, lo, hi);
    lo = __shfl_xor_sync(0xffffffffu, lo, m);
    hi = __shfl_xor_sync(0xffffffffu, hi, m);
    return pk2(lo, hi);
}

// Exact power-of-2 rescale factor from a stale probe value d (pure ALU).
__device__ __forceinline__ float po2_rescale(float d, int& eacc){
    unsigned u = __float_as_uint(d);
    int e = (int)(u >> 23) & 0xff;
    if (e == 0 || e >= 254) return 1.0f;
    eacc += (e - 127);
    return __uint_as_float((unsigned)(254 - e) << 23);
}

// Exp-domain CRF forward, k-quarter split: 1 warp = 1 batch (2048 warps).
// lane = (class-quad gc in 0..7) x (k-quarter kq in 0..3). Each lane holds P
// for its 4 classes (duplicated across kq copies) and computes 4 partial dots
// over its 8 k's (16 FFMA2/step, 2-deep chains). Exchange reads ONLY kq=0
// copies (8 SHFL); partner reduction is a flat 1-round gather (12 SHFL).
// Cross-copy rounding divergence is harmless: nothing reads kq!=0 state.
// Numerics: exp-domain, blend-then-po2-rescale every 4 steps, stale pivot.
__global__ __launch_bounds__(32, 16)
void crf_fwd(const float* __restrict__ feats,
             const float* __restrict__ mask,
             const float* __restrict__ trans,
             float* __restrict__ out,
             int seq, int batch)
{
    const int lane = threadIdx.x & 31;
    const int gc   = lane & 7;        // class quad -> classes 4gc..4gc+3
    const int kq   = lane >> 3;       // k-quarter: k in [8kq, 8kq+8)
    const int c0   = gc * 4;
    const int k0   = kq * 8;
    const int bb   = blockIdx.x;      // 1 batch per warp
    const int src0 = 2 * kq;          // kq=0 lane holding classes 8kq..8kq+3
    const int src1 = 2 * kq + 1;      // kq=0 lane holding classes 8kq+4..8kq+7

    // E2[ci][kp] = (exp T[c0+ci][k0+2kp], exp T[c0+ci][k0+2kp+1])  (16 u64)
    u64 E2[4][4];
#pragma unroll
    for (int ci = 0; ci < 4; ++ci){
        const float* tr = trans + (c0 + ci) * NCLS + k0;
#pragma unroll
        for (int kp = 0; kp < 4; ++kp)
            E2[ci][kp] = pk2(ex2f(tr[2*kp] * LOG2E), ex2f(tr[2*kp+1] * LOG2E));
    }
    u64 ee2[2];
    {
        const float* te = trans + EOSC * NCLS + c0;
        ee2[0] = pk2(ex2f(te[0]*LOG2E), ex2f(te[1]*LOG2E));
        ee2[1] = pk2(ex2f(te[2]*LOG2E), ex2f(te[3]*LOG2E));
    }

    // State: P for this lane's 4 classes (duplicated across kq copies).
    u64 P2[2];
    P2[0] = pk2((c0+0==SOSC)?1.f:0.f, (c0+1==SOSC)?1.f:0.f);
    P2[1] = pk2((c0+2==SOSC)?1.f:0.f, (c0+3==SOSC)?1.f:0.f);
    int eC = 0;                       // exact integer log2 offset

    const float* fbase = feats + (size_t)bb * NCLS + c0;
    const float* mbase = mask + bb;
    const unsigned fstep = (unsigned)batch * NCLS;
    const unsigned mstep = (unsigned)batch;

    // 8-deep prefetch of exp(feat) (4 classes/lane) and pre-packed mask.
    u64 fe[8][2], mm[8];
#pragma unroll
    for (int j = 0; j < 8; ++j){
        int tc = (j < seq) ? j : (seq - 1);
        float4 f4 = *reinterpret_cast<const float4*>(fbase + (size_t)((unsigned)tc * fstep));
        fe[j][0] = pk2(ex2f(f4.x*LOG2E), ex2f(f4.y*LOG2E));
        fe[j][1] = pk2(ex2f(f4.z*LOG2E), ex2f(f4.w*LOG2E));
        float m = mbase[(unsigned)tc * mstep];
        mm[j] = pk2(m, m);
    }

    int t0 = 0;
    for (; t0 + 8 <= seq; t0 += 8){
#pragma unroll
        for (int j = 0; j < 8; ++j){
            // stale rescale pivot: P[class 0] (lane 0), pure ALU + 1 shfl
            float r = 1.0f;
            if ((j & 3) == 0){
                float plo, phi; up2(P2[0], plo, phi);
                float piv = __shfl_sync(0xffffffffu, plo, 0);
                r = po2_rescale(piv, eC);
            }
            // exchange: this lane's 8 k-values, from kq=0 copies (8 SHFL)
            u64 q0 = shfl64(P2[0], src0);
            u64 q1 = shfl64(P2[1], src0);
            u64 q2 = shfl64(P2[0], src1);
            u64 q3 = shfl64(P2[1], src1);
            // 4 partial dots over this k-quarter (16 FFMA2, 2-deep chains)
            float s[4];
#pragma unroll
            for (int ci = 0; ci < 4; ++ci){
                u64 aA = ffma2(E2[ci][0], q0, 0ull);
                u64 aB = ffma2(E2[ci][1], q1, 0ull);
                aA = ffma2(E2[ci][2], q2, aA);
                aB = ffma2(E2[ci][3], q3, aB);
                u64 a = fadd2(aA, aB);
                float lo, hi; up2(a, lo, hi);
                s[ci] = lo + hi;
            }
            u64 s01 = pk2(s[0], s[1]);
            u64 s23 = pk2(s[2], s[3]);
            // flat 1-round gather over the 4 kq copies (independent shfls)
            u64 b1 = shfl64x(s01, 8), b2 = shfl64x(s01, 16), b3 = shfl64x(s01, 24);
            s01 = fadd2(fadd2(s01, b1), fadd2(b2, b3));
            u64 c1 = shfl64x(s23, 8), c2 = shfl64x(s23, 16), c3 = shfl64x(s23, 24);
            s23 = fadd2(fadd2(s23, c1), fadd2(c2, c3));
            u64 Pn0 = fmul2(s01, fe[j][0]);
            u64 Pn1 = fmul2(s23, fe[j][1]);
            // blend first (operands share one scale; exact for mask in {0,1})
            P2[0] = ffma2(mm[j], fsub2(Pn0, P2[0]), P2[0]);
            P2[1] = ffma2(mm[j], fsub2(Pn1, P2[1]), P2[1]);
            // then uniform po2 rescale of the blended state
            if ((j & 3) == 0){
                u64 rr = pk2(r, r);
                P2[0] = fmul2(P2[0], rr);
                P2[1] = fmul2(P2[1], rr);
            }
            // prefetch step t0+8+j (index clamped BEFORE offset computation)
            {
                int tn = t0 + 8 + j;
                int tc = (tn < seq) ? tn : (seq - 1);
                float4 f4 = *reinterpret_cast<const float4*>(fbase + (size_t)((unsigned)tc * fstep));
                fe[j][0] = pk2(ex2f(f4.x*LOG2E), ex2f(f4.y*LOG2E));
                fe[j][1] = pk2(ex2f(f4.z*LOG2E), ex2f(f4.w*LOG2E));
                float m = mbase[(unsigned)tc * mstep];
                mm[j] = pk2(m, m);
            }
        }
    }
    // tail (seq % 8 != 0; not hit for seq=512)
    for (int t = t0; t < seq; ++t){
        u64 q0 = shfl64(P2[0], src0);
        u64 q1 = shfl64(P2[1], src0);
        u64 q2 = shfl64(P2[0], src1);
        u64 q3 = shfl64(P2[1], src1);
        float s[4];
#pragma unroll
        for (int ci = 0; ci < 4; ++ci){
            u64 aA = ffma2(E2[ci][0], q0, 0ull);
            u64 aB = ffma2(E2[ci][1], q1, 0ull);
            aA = ffma2(E2[ci][2], q2, aA);
            aB = ffma2(E2[ci][3], q3, aB);
            u64 a = fadd2(aA, aB);
            float lo, hi; up2(a, lo, hi);
            s[ci] = lo + hi;
        }
        u64 s01 = pk2(s[0], s[1]);
        u64 s23 = pk2(s[2], s[3]);
        u64 b1 = shfl64x(s01, 8), b2 = shfl64x(s01, 16), b3 = shfl64x(s01, 24);
        s01 = fadd2(fadd2(s01, b1), fadd2(b2, b3));
        u64 c1 = shfl64x(s23, 8), c2 = shfl64x(s23, 16), c3 = shfl64x(s23, 24);
        s23 = fadd2(fadd2(s23, c1), fadd2(c2, c3));
        float4 f4 = *reinterpret_cast<const float4*>(fbase + (size_t)((unsigned)t * fstep));
        u64 Pn0 = fmul2(s01, pk2(ex2f(f4.x*LOG2E), ex2f(f4.y*LOG2E)));
        u64 Pn1 = fmul2(s23, pk2(ex2f(f4.z*LOG2E), ex2f(f4.w*LOG2E)));
        float m = mbase[(unsigned)t * mstep];
        u64 mv = pk2(m, m);
        P2[0] = ffma2(mv, fsub2(Pn0, P2[0]), P2[0]);
        P2[1] = ffma2(mv, fsub2(Pn1, P2[1]), P2[1]);
        {   // rescale every tail step
            float plo, phi; up2(P2[0], plo, phi);
            float piv = __shfl_sync(0xffffffffu, plo, 0);
            float r = po2_rescale(piv, eC);
            u64 rr = pk2(r, r);
            P2[0] = fmul2(P2[0], rr);
            P2[1] = fmul2(P2[1], rr);
        }
    }

    // Epilogue: out[bb] = ln2 * (eC + log2( sum_c P[c] * exp(T[EOS,c]) ))
    u64 w2 = fmul2(P2[0], ee2[0]);
    w2 = ffma2(P2[1], ee2[1], w2);
    float lo, hi; up2(w2, lo, hi);
    float v = lo + hi;                 // sum over this lane's 4 classes
    // reduce over the 8 class quads (within each kq copy)
    v += __shfl_xor_sync(0xffffffffu, v, 1);
    v += __shfl_xor_sync(0xffffffffu, v, 2);
    v += __shfl_xor_sync(0xffffffffu, v, 4);
    if (lane == 0)
        out[bb] = ((float)eC + lg2f_(v)) * LN2F;
}

extern "C" void kernel_launch(void* const* d_in, const int* in_sizes, int n_in,
                              void* d_out, int out_size)
{
    const float* feats = (const float*)d_in[0];
    const float* mask  = (const float*)d_in[1];
    const float* trans = (const float*)d_in[2];
    float* out = (float*)d_out;

    const int batch = out_size;                 // out is (batch,)
    const int seq   = in_sizes[1] / batch;      // mask is (seq, batch)

    // 1 warp per batch: batch warps (2048), maximal latency hiding
    crf_fwd<<<batch, 32>>>(feats, mask, trans, out, seq, batch);
}

// round 11
// speedup vs baseline: 1.2130x; 1.2130x over previous
#include <cuda_runtime.h>

#define NCLS 32
#define SOSC 30
#define EOSC 31
#define LOG2E 1.4426950408889634f
#define LN2F  0.6931471805599453f

typedef unsigned long long u64;

__device__ __forceinline__ float ex2f(float x){ float r; asm("ex2.approx.f32 %0, %1;" : "=f"(r) : "f"(x)); return r; }
__device__ __forceinline__ float lg2f_(float x){ float r; asm("lg2.approx.f32 %0, %1;" : "=f"(r) : "f"(x)); return r; }
__device__ __forceinline__ u64 pk2(float lo, float hi){ u64 r; asm("mov.b64 %0, {%1,%2};" : "=l"(r) : "f"(lo), "f"(hi)); return r; }
__device__ __forceinline__ void up2(u64 v, float& lo, float& hi){ asm("mov.b64 {%0,%1}, %2;" : "=f"(lo), "=f"(hi) : "l"(v)); }
__device__ __forceinline__ u64 ffma2(u64 a, u64 b, u64 c){ u64 d; asm("fma.rn.f32x2 %0, %1, %2, %3;" : "=l"(d) : "l"(a), "l"(b), "l"(c)); return d; }
__device__ __forceinline__ u64 fadd2(u64 a, u64 b){ u64 d; asm("add.rn.f32x2 %0, %1, %2;" : "=l"(d) : "l"(a), "l"(b)); return d; }
__device__ __forceinline__ u64 fmul2(u64 a, u64 b){ u64 d; asm("mul.rn.f32x2 %0, %1, %2;" : "=l"(d) : "l"(a), "l"(b)); return d; }
__device__ __forceinline__ u64 fsub2(u64 a, u64 b){ u64 d; asm("sub.rn.f32x2 %0, %1, %2;" : "=l"(d) : "l"(a), "l"(b)); return d; }

// 64-bit idx-shuffle via two independent 32-bit shfl.idx.
__device__ __forceinline__ u64 shfl64(u64 v, int src){
    float lo, hi; up2(v, lo, hi);
    lo = __shfl_sync(0xffffffffu, lo, src);
    hi = __shfl_sync(0xffffffffu, hi, src);
    return pk2(lo, hi);
}

// Exact power-of-2 rescale factor from a stale probe value d (pure ALU).
__device__ __forceinline__ float po2_rescale(float d, int& eacc){
    unsigned u = __float_as_uint(d);
    int e = (int)(u >> 23) & 0xff;
    if (e == 0 || e >= 254) return 1.0f;
    eacc += (e - 127);
    return __uint_as_float((unsigned)(254 - e) << 23);
}

// Exp-domain CRF forward. 1 warp = 2 batches; 16 lanes/batch; each lane owns
// 2 classes (2h, 2h+1) and computes their FULL 32-k dots (no partner round).
// Exchange: q[kp] = P-pair of lane ((lane&16)|kp) — 16 shfl64. k-packed f32x2
// throughout; horizontal sum only at the end of each dot.
// Numerics: exp-domain, blend-then-exact-po2-rescale every 4 steps (stale
// pivot, ALU-only), proven in rounds 6-9.
__global__ __launch_bounds__(32, 8)
void crf_fwd(const float* __restrict__ feats,
             const float* __restrict__ mask,
             const float* __restrict__ trans,
             float* __restrict__ out,
             int seq, int batch)
{
    const int lane = threadIdx.x & 31;
    const int b    = lane >> 4;       // batch slot (0..1)
    const int h    = lane & 15;       // class-pair index: classes 2h, 2h+1
    const int c0   = 2 * h;
    const int batch0 = blockIdx.x * 2;
    int bb = batch0 + b;
    const bool real = (bb < batch);
    if (!real) bb = batch - 1;
    const int xbase = lane & 16;      // lane holding P-pair kp of this batch

    // E2[ci][kp] = (exp T[c0+ci][2kp], exp T[c0+ci][2kp+1])  (32 u64)
    u64 E2[2][16];
#pragma unroll
    for (int ci = 0; ci < 2; ++ci){
        const float* tr = trans + (c0 + ci) * NCLS;
#pragma unroll
        for (int kp = 0; kp < 16; ++kp)
            E2[ci][kp] = pk2(ex2f(tr[2*kp] * LOG2E), ex2f(tr[2*kp+1] * LOG2E));
    }
    u64 ee2;   // (exp T[EOS][c0], exp T[EOS][c0+1])
    {
        const float* te = trans + EOSC * NCLS + c0;
        ee2 = pk2(ex2f(te[0]*LOG2E), ex2f(te[1]*LOG2E));
    }

    // State: P for this lane's 2 classes, k-packed-compatible pair.
    u64 P2 = pk2((c0+0==SOSC)?1.f:0.f, (c0+1==SOSC)?1.f:0.f);
    int eC = 0;                       // exact integer log2 offset

    const float* fbase = feats + (size_t)bb * NCLS + c0;
    const float* mbase = mask + bb;
    const unsigned fstep = (unsigned)batch * NCLS;
    const unsigned mstep = (unsigned)batch;

    // 8-deep prefetch: fe = (exp f[c0], exp f[c0+1]) via LDG.64; mask scalar.
    u64 fe[8]; float mk[8];
#pragma unroll
    for (int j = 0; j < 8; ++j){
        int tc = (j < seq) ? j : (seq - 1);
        float2 f2 = *reinterpret_cast<const float2*>(fbase + (size_t)((unsigned)tc * fstep));
        fe[j] = pk2(ex2f(f2.x*LOG2E), ex2f(f2.y*LOG2E));
        mk[j] = mbase[(unsigned)tc * mstep];
    }

    int t0 = 0;
    for (; t0 + 8 <= seq; t0 += 8){
#pragma unroll
        for (int j = 0; j < 8; ++j){
            // stale rescale pivot: P[class 0] of this batch (lane b*16)
            float r = 1.0f;
            if ((j & 3) == 0){
                float plo, phi; up2(P2, plo, phi);
                float piv = __shfl_sync(0xffffffffu, plo, xbase);
                r = po2_rescale(piv, eC);
            }
            // exchange: q[kp] = (P[2kp], P[2kp+1]) from lane xbase|kp
            u64 q[16];
#pragma unroll
            for (int kp = 0; kp < 16; ++kp)
                q[kp] = shfl64(P2, xbase + kp);
            // two full 32-k dots (32 ffma2), 4 chains of depth 4 each class
            u64 a0, a1, a2, a3, b0, b1, b2, b3;
            a0 = ffma2(E2[0][0],  q[0],  0ull);
            a1 = ffma2(E2[0][1],  q[1],  0ull);
            a2 = ffma2(E2[0][2],  q[2],  0ull);
            a3 = ffma2(E2[0][3],  q[3],  0ull);
            b0 = ffma2(E2[1][0],  q[0],  0ull);
            b1 = ffma2(E2[1][1],  q[1],  0ull);
            b2 = ffma2(E2[1][2],  q[2],  0ull);
            b3 = ffma2(E2[1][3],  q[3],  0ull);
#pragma unroll
            for (int kp = 4; kp < 16; kp += 4){
                a0 = ffma2(E2[0][kp],   q[kp],   a0);
                a1 = ffma2(E2[0][kp+1], q[kp+1], a1);
                a2 = ffma2(E2[0][kp+2], q[kp+2], a2);
                a3 = ffma2(E2[0][kp+3], q[kp+3], a3);
                b0 = ffma2(E2[1][kp],   q[kp],   b0);
                b1 = ffma2(E2[1][kp+1], q[kp+1], b1);
                b2 = ffma2(E2[1][kp+2], q[kp+2], b2);
                b3 = ffma2(E2[1][kp+3], q[kp+3], b3);
            }
            u64 sa = fadd2(fadd2(a0, a1), fadd2(a2, a3));
            u64 sb = fadd2(fadd2(b0, b1), fadd2(b2, b3));
            float sa0, sa1, sb0, sb1;
            up2(sa, sa0, sa1); up2(sb, sb0, sb1);
            u64 Pn = fmul2(pk2(sa0 + sa1, sb0 + sb1), fe[j]);
            // blend first (operands share one scale; exact for mask in {0,1})
            u64 mm = pk2(mk[j], mk[j]);
            P2 = ffma2(mm, fsub2(Pn, P2), P2);
            // then uniform po2 rescale of the blended state
            if ((j & 3) == 0)
                P2 = fmul2(P2, pk2(r, r));
            // prefetch step t0+8+j (index clamped BEFORE offset computation)
            {
                int tn = t0 + 8 + j;
                int tc = (tn < seq) ? tn : (seq - 1);
                float2 f2 = *reinterpret_cast<const float2*>(fbase + (size_t)((unsigned)tc * fstep));
                fe[j] = pk2(ex2f(f2.x*LOG2E), ex2f(f2.y*LOG2E));
                mk[j] = mbase[(unsigned)tc * mstep];
            }
        }
    }
    // tail (seq % 8 != 0; not hit for seq=512)
    for (int t = t0; t < seq; ++t){
        u64 q[16];
#pragma unroll
        for (int kp = 0; kp < 16; ++kp)
            q[kp] = shfl64(P2, xbase + kp);
        u64 a0 = 0ull, a1 = 0ull, b0 = 0ull, b1 = 0ull;
#pragma unroll
        for (int kp = 0; kp < 16; kp += 2){
            a0 = ffma2(E2[0][kp],   q[kp],   a0);
            a1 = ffma2(E2[0][kp+1], q[kp+1], a1);
            b0 = ffma2(E2[1][kp],   q[kp],   b0);
            b1 = ffma2(E2[1][kp+1], q[kp+1], b1);
        }
        u64 sa = fadd2(a0, a1), sb = fadd2(b0, b1);
        float sa0, sa1, sb0, sb1;
        up2(sa, sa0, sa1); up2(sb, sb0, sb1);
        float2 f2 = *reinterpret_cast<const float2*>(fbase + (size_t)((unsigned)t * fstep));
        u64 Pn = fmul2(pk2(sa0 + sa1, sb0 + sb1),
                       pk2(ex2f(f2.x*LOG2E), ex2f(f2.y*LOG2E)));
        float m = mbase[(unsigned)t * mstep];
        u64 mm = pk2(m, m);
        P2 = ffma2(mm, fsub2(Pn, P2), P2);
        {   // rescale every tail step
            float plo, phi; up2(P2, plo, phi);
            float piv = __shfl_sync(0xffffffffu, plo, xbase);
            float r = po2_rescale(piv, eC);
            P2 = fmul2(P2, pk2(r, r));
        }
    }

    // Epilogue: out[bb] = ln2 * (eC + log2( sum_c P[c] * exp(T[EOS,c]) ))
    u64 w2 = fmul2(P2, ee2);
    float lo, hi; up2(w2, lo, hi);
    float v = lo + hi;                 // this lane's 2 classes
    // reduce over the 16 class-pair lanes of this batch half
    v += __shfl_xor_sync(0xffffffffu, v, 1);
    v += __shfl_xor_sync(0xffffffffu, v, 2);
    v += __shfl_xor_sync(0xffffffffu, v, 4);
    v += __shfl_xor_sync(0xffffffffu, v, 8);
    if (h == 0 && real)
        out[bb] = ((float)eC + lg2f_(v)) * LN2F;
}

extern "C" void kernel_launch(void* const* d_in, const int* in_sizes, int n_in,
                              void* d_out, int out_size)
{
    const float* feats = (const float*)d_in[0];
    const float* mask  = (const float*)d_in[1];
    const float* trans = (const float*)d_in[2];
    float* out = (float*)d_out;

    const int batch = out_size;                 // out is (batch,)
    const int seq   = in_sizes[1] / batch;      // mask is (seq, batch)

    const int blocks = (batch + 1) / 2;         // 1 warp = 2 batches
    crf_fwd<<<blocks, 32>>>(feats, mask, trans, out, seq, batch);
}